// round 3
// baseline (speedup 1.0000x reference)
#include <cuda_runtime.h>
#include <math.h>

#define BB   2
#define HH   8
#define LL   4096
#define DMM  512
#define DHH  64
#define NBB  64
#define BSS  64
#define KPQ  9

typedef unsigned long long u64;

__device__ float g_q[BB*HH*LL*DHH];
__device__ float g_k[BB*HH*LL*DHH];
__device__ float g_v[BB*HH*LL*DHH];
__device__ float g_qproj[BB*HH*NBB*DHH];
__device__ float g_kproj[BB*HH*NBB*DHH];
__device__ float g_pbias[HH*NBB*NBB];
__device__ int   g_sel[BB*HH*NBB*KPQ];
__device__ float g_sparse[BB*HH*LL*DHH];
__device__ float g_kv[BB*HH*DHH*DHH];
__device__ float g_ksum[BB*HH*DHH];
__device__ float g_blend[BB*LL*DMM];

__device__ __forceinline__ u64 dup2(float x) {
    u64 r; asm("mov.b64 %0, {%1, %1};" : "=l"(r) : "f"(x)); return r;
}
__device__ __forceinline__ void fma2(u64& d, u64 a, u64 b) {
    asm("fma.rn.f32x2 %0, %1, %2, %0;" : "+l"(d) : "l"(a), "l"(b));
}
__device__ __forceinline__ float2 unp2(u64 v) {
    float lo, hi; asm("mov.b64 {%0, %1}, %2;" : "=f"(lo), "=f"(hi) : "l"(v));
    return make_float2(lo, hi);
}

// ---- C = X @ W^T. CTA tile 64m x 128n, thread tile 4x8 via f32x2 ----
// mode 0: row-major out, N = gridDim.x*128 ; mode 1: BHLD layout
__global__ void __launch_bounds__(256) gemm_xwt_kernel(
        const float* __restrict__ X, const float* __restrict__ W,
        float* __restrict__ outp, int K, int mode) {
    __shared__ float Xs[16][68];
    __shared__ float Ws[16][132];
    int t = threadIdx.x;
    int tx = t & 15, ty = t >> 4;
    int m0 = blockIdx.y << 6, n0 = blockIdx.x << 7;
    u64 acc[4][4];
#pragma unroll
    for (int i = 0; i < 4; i++)
#pragma unroll
        for (int j = 0; j < 4; j++) acc[i][j] = 0ull;

    int lr = t >> 2, lk = (t & 3) << 2;
    const float* Xp  = X + (size_t)(m0 + lr) * K + lk;
    const float* Wp1 = W + (size_t)(n0 + lr) * K + lk;
    const float* Wp2 = W + (size_t)(n0 + 64 + lr) * K + lk;

    for (int k0 = 0; k0 < K; k0 += 16) {
        float4 xa = *(const float4*)(Xp + k0);
        float4 w1 = *(const float4*)(Wp1 + k0);
        float4 w2 = *(const float4*)(Wp2 + k0);
        __syncthreads();
        Xs[lk+0][lr]=xa.x; Xs[lk+1][lr]=xa.y; Xs[lk+2][lr]=xa.z; Xs[lk+3][lr]=xa.w;
        Ws[lk+0][lr]=w1.x; Ws[lk+1][lr]=w1.y; Ws[lk+2][lr]=w1.z; Ws[lk+3][lr]=w1.w;
        Ws[lk+0][lr+64]=w2.x; Ws[lk+1][lr+64]=w2.y; Ws[lk+2][lr+64]=w2.z; Ws[lk+3][lr+64]=w2.w;
        __syncthreads();
#pragma unroll
        for (int kk = 0; kk < 16; kk++) {
            float4 a = *(const float4*)&Xs[kk][ty << 2];
            ulonglong2 b0 = *(const ulonglong2*)&Ws[kk][tx << 3];
            ulonglong2 b1 = *(const ulonglong2*)&Ws[kk][(tx << 3) + 4];
            u64 a0 = dup2(a.x), a1 = dup2(a.y), a2 = dup2(a.z), a3 = dup2(a.w);
            fma2(acc[0][0],a0,b0.x); fma2(acc[0][1],a0,b0.y); fma2(acc[0][2],a0,b1.x); fma2(acc[0][3],a0,b1.y);
            fma2(acc[1][0],a1,b0.x); fma2(acc[1][1],a1,b0.y); fma2(acc[1][2],a1,b1.x); fma2(acc[1][3],a1,b1.y);
            fma2(acc[2][0],a2,b0.x); fma2(acc[2][1],a2,b0.y); fma2(acc[2][2],a2,b1.x); fma2(acc[2][3],a2,b1.y);
            fma2(acc[3][0],a3,b0.x); fma2(acc[3][1],a3,b0.y); fma2(acc[3][2],a3,b1.x); fma2(acc[3][3],a3,b1.y);
        }
    }
    float o[4][8];
#pragma unroll
    for (int ii = 0; ii < 4; ii++)
#pragma unroll
        for (int jp = 0; jp < 4; jp++) {
            float2 v = unp2(acc[ii][jp]);
            o[ii][2*jp] = v.x; o[ii][2*jp+1] = v.y;
        }
    if (mode == 0) {
        int N = gridDim.x << 7;
#pragma unroll
        for (int ii = 0; ii < 4; ii++) {
            float* dp = outp + (size_t)(m0 + (ty<<2) + ii) * N + n0 + (tx<<3);
            *(float4*)dp       = make_float4(o[ii][0], o[ii][1], o[ii][2], o[ii][3]);
            *(float4*)(dp + 4) = make_float4(o[ii][4], o[ii][5], o[ii][6], o[ii][7]);
        }
    } else {
        int nabs = n0 + (tx << 3);
        int h = nabs >> 6, col = nabs & 63;
#pragma unroll
        for (int ii = 0; ii < 4; ii++) {
            int m = m0 + (ty<<2) + ii;
            int b = m >> 12, l = m & 4095;
            float* dp = outp + (((size_t)(b*HH + h) * LL + l) << 6) + col;
            *(float4*)dp       = make_float4(o[ii][0], o[ii][1], o[ii][2], o[ii][3]);
            *(float4*)(dp + 4) = make_float4(o[ii][4], o[ii][5], o[ii][6], o[ii][7]);
        }
    }
}

// ---- block pooling + router projections (256 thr, split rows) ----
__global__ void pool_proj_kernel(const float* __restrict__ Wrq, const float* __restrict__ Wrk) {
    int qb = blockIdx.x, bh = blockIdx.y;
    int t = threadIdx.x;
    int d = t & 63, g = t >> 6;
    __shared__ float sq[4][64], sk[4][64];
    __shared__ float qp[64], kp[64];
    const float* qb_ = g_q + ((size_t)bh * LL + qb * BSS + g * 16) * DHH;
    const float* kb_ = g_k + ((size_t)bh * LL + qb * BSS + g * 16) * DHH;
    float aq = 0.f, ak = 0.f;
#pragma unroll 4
    for (int i = 0; i < 16; i++) { aq += qb_[i*DHH + d]; ak += kb_[i*DHH + d]; }
    sq[g][d] = aq; sk[g][d] = ak;
    __syncthreads();
    if (t < 64) {
        qp[d] = (sq[0][d]+sq[1][d]+sq[2][d]+sq[3][d]) * (1.f / BSS);
        kp[d] = (sk[0][d]+sk[1][d]+sk[2][d]+sk[3][d]) * (1.f / BSS);
    }
    __syncthreads();
    float pq = 0.f, pk2 = 0.f;
#pragma unroll 4
    for (int e = g*16; e < g*16 + 16; e++) {
        pq  += qp[e] * Wrq[d*DHH + e];
        pk2 += kp[e] * Wrk[d*DHH + e];
    }
    sq[g][d] = pq; sk[g][d] = pk2;
    __syncthreads();
    if (t < 64) {
        g_qproj[((size_t)bh * NBB + qb) * DHH + d] = sq[0][d]+sq[1][d]+sq[2][d]+sq[3][d];
        g_kproj[((size_t)bh * NBB + qb) * DHH + d] = sk[0][d]+sk[1][d]+sk[2][d]+sk[3][d];
    }
}

__global__ void pool_bias_kernel(const float* __restrict__ pb) {
    int h = blockIdx.y;
    int qb = blockIdx.x >> 6, kb = blockIdx.x & 63;
    const float* base = pb + ((size_t)h * LL + qb * BSS) * LL + kb * BSS;
    int t = threadIdx.x;
    int j = t & 63, i0 = t >> 6;
    float s = 0.f;
    for (int i = i0; i < BSS; i += 2) s += base[(size_t)i * LL + j];
    __shared__ float red[128];
    red[t] = s;
    __syncthreads();
    if (t < 64) red[t] += red[t + 64];
    __syncthreads();
    if (t < 32) {
        float v = red[t] + red[t + 32];
        for (int o = 16; o; o >>= 1) v += __shfl_xor_sync(0xffffffffu, v, o);
        if (t == 0) g_pbias[((size_t)h * NBB + qb) * NBB + kb] = v * (1.f / (BSS * BSS));
    }
}

__global__ void router_topk_kernel(const float* __restrict__ bscale_p) {
    __shared__ float sc[NBB][NBB];
    int bh = blockIdx.x;
    int h = bh & 7;
    float bsc = *bscale_p;
    const float* qp = g_qproj + (size_t)bh * NBB * DHH;
    const float* kp = g_kproj + (size_t)bh * NBB * DHH;
    for (int e = threadIdx.x; e < NBB * NBB; e += 256) {
        int qb = e >> 6, kb = e & 63;
        float s = 0.f;
        for (int d = 0; d < DHH; d++) s += qp[qb*DHH + d] * kp[kb*DHH + d];
        sc[qb][kb] = s * 0.125f + bsc * g_pbias[((size_t)h * NBB + qb) * NBB + kb];
    }
    __syncthreads();
    int warp = threadIdx.x >> 5, lane = threadIdx.x & 31;
    for (int r = warp; r < NBB; r += 8) {
        float v0 = sc[r][lane], v1 = sc[r][lane + 32];
        int i0 = lane, i1 = lane + 32;
        for (int tk = 0; tk < KPQ; tk++) {
            float bv; int bi;
            if (v0 > v1 || (v0 == v1 && i0 < i1)) { bv = v0; bi = i0; }
            else { bv = v1; bi = i1; }
            for (int off = 16; off; off >>= 1) {
                float ov = __shfl_xor_sync(0xffffffffu, bv, off);
                int   oi = __shfl_xor_sync(0xffffffffu, bi, off);
                if (ov > bv || (ov == bv && oi < bi)) { bv = ov; bi = oi; }
            }
            if (lane == 0) g_sel[((size_t)bh * NBB + r) * KPQ + tk] = bi;
            if (i0 == bi) v0 = -INFINITY;
            if (i1 == bi) v1 = -INFINITY;
        }
    }
}

__device__ __forceinline__ float fq_clip(float r) {
    return fminf(fmaxf(r, -128.f), 127.f);
}

__device__ __forceinline__ void load_fq_block(const float* __restrict__ src_base,
                                              float* __restrict__ dst,
                                              int lrow, int lg, int transpose) {
    const float* src = src_base + (size_t)lrow * DHH + lg * 16;
    float x[16];
    float mx = 0.f;
#pragma unroll
    for (int c = 0; c < 16; c += 4) {
        float4 v = *(const float4*)(src + c);
        x[c] = v.x; x[c+1] = v.y; x[c+2] = v.z; x[c+3] = v.w;
    }
#pragma unroll
    for (int c = 0; c < 16; c++) mx = fmaxf(mx, fabsf(x[c]));
    mx = fmaxf(mx, __shfl_xor_sync(0xffffffffu, mx, 1));
    mx = fmaxf(mx, __shfl_xor_sync(0xffffffffu, mx, 2));
    float scale = fmaxf(mx, 1e-8f) / 127.0f;
    if (transpose) {
#pragma unroll
        for (int c = 0; c < 16; c++)
            dst[(lg*16 + c) * 68 + lrow] = fq_clip(rintf(x[c] / scale)) * scale;
    } else {
#pragma unroll
        for (int c = 0; c < 16; c += 4) {
            float4 o;
            o.x = fq_clip(rintf(x[c  ] / scale)) * scale;
            o.y = fq_clip(rintf(x[c+1] / scale)) * scale;
            o.z = fq_clip(rintf(x[c+2] / scale)) * scale;
            o.w = fq_clip(rintf(x[c+3] / scale)) * scale;
            *(float4*)&dst[lrow * 68 + lg*16 + c] = o;
        }
    }
}

#define SMEM_K5 ((576*68 + 64*68 + 64*68 + 192) * 4)

__global__ void sparse_attn_kernel(const float* __restrict__ pb) {
    extern __shared__ float sm[];
    float* ST   = sm;
    float* qsT  = ST  + 576 * 68;
    float* kvb  = qsT + 64 * 68;
    float* rowm = kvb + 64 * 68;
    float* rowz = rowm + 64;
    float* rowsc= rowz + 64;

    int qb = blockIdx.x, bh = blockIdx.y;
    int h = bh & 7;
    int t = threadIdx.x;
    int tx = t & 15, ty = t >> 4;
    int lrow = t >> 2, lg = t & 3;

    load_fq_block(g_q + ((size_t)bh * LL + qb * BSS) * DHH, qsT, lrow, lg, 1);
    __syncthreads();

    const int selbase = (bh * NBB + qb) * KPQ;
    int i0 = ty << 2, j0 = tx << 2;

    for (int kb = 0; kb < KPQ; kb++) {
        int kidx = g_sel[selbase + kb];
        load_fq_block(g_k + ((size_t)bh * LL + kidx * BSS) * DHH, kvb, lrow, lg, 1);
        __syncthreads();
        u64 acc[4][2];
#pragma unroll
        for (int i = 0; i < 4; i++) { acc[i][0] = 0ull; acc[i][1] = 0ull; }
#pragma unroll 8
        for (int d = 0; d < 64; d++) {
            float4 a = *(const float4*)&qsT[d*68 + i0];
            ulonglong2 b = *(const ulonglong2*)&kvb[d*68 + j0];
            u64 a0 = dup2(a.x), a1 = dup2(a.y), a2 = dup2(a.z), a3 = dup2(a.w);
            fma2(acc[0][0],a0,b.x); fma2(acc[0][1],a0,b.y);
            fma2(acc[1][0],a1,b.x); fma2(acc[1][1],a1,b.y);
            fma2(acc[2][0],a2,b.x); fma2(acc[2][1],a2,b.y);
            fma2(acc[3][0],a3,b.x); fma2(acc[3][1],a3,b.y);
        }
        float facc[4][4];
#pragma unroll
        for (int ii = 0; ii < 4; ii++) {
            float2 v0 = unp2(acc[ii][0]), v1 = unp2(acc[ii][1]);
            facc[ii][0]=v0.x; facc[ii][1]=v0.y; facc[ii][2]=v1.x; facc[ii][3]=v1.y;
        }
        const float* brow = pb + ((size_t)h * LL + qb * BSS + i0) * LL + (size_t)kidx * BSS + j0;
#pragma unroll
        for (int ii = 0; ii < 4; ii++) {
            float4 pv = *(const float4*)(brow + (size_t)ii * LL);
            facc[ii][0] += pv.x; facc[ii][1] += pv.y; facc[ii][2] += pv.z; facc[ii][3] += pv.w;
        }
#pragma unroll
        for (int jj = 0; jj < 4; jj++)
            *(float4*)&ST[(kb*64 + j0 + jj) * 68 + i0] =
                make_float4(facc[0][jj], facc[1][jj], facc[2][jj], facc[3][jj]);
        __syncthreads();
    }

    {
        float m = -INFINITY;
        for (int j = lg; j < 576; j += 4) m = fmaxf(m, ST[j*68 + lrow]);
        m = fmaxf(m, __shfl_xor_sync(0xffffffffu, m, 1));
        m = fmaxf(m, __shfl_xor_sync(0xffffffffu, m, 2));
        float z = 0.f;
        for (int j = lg; j < 576; j += 4) z += expf(ST[j*68 + lrow] - m);
        z += __shfl_xor_sync(0xffffffffu, z, 1);
        z += __shfl_xor_sync(0xffffffffu, z, 2);
        if (lg == 0) {
            rowm[lrow] = m; rowz[lrow] = z;
            rowsc[lrow] = fmaxf(1.0f / z, 1e-8f) / 127.0f;
        }
    }
    __syncthreads();

    for (int e = t; e < 576 * 64; e += 256) {
        int i = e & 63, j = e >> 6;
        float w = expf(ST[j*68 + i] - rowm[i]) / rowz[i];
        float sc = rowsc[i];
        ST[j*68 + i] = fq_clip(rintf(w / sc)) * sc;
    }
    __syncthreads();

    u64 acc2[4][2];
#pragma unroll
    for (int i = 0; i < 4; i++) { acc2[i][0] = 0ull; acc2[i][1] = 0ull; }
    for (int kb = 0; kb < KPQ; kb++) {
        int kidx = g_sel[selbase + kb];
        load_fq_block(g_v + ((size_t)bh * LL + kidx * BSS) * DHH, kvb, lrow, lg, 0);
        __syncthreads();
#pragma unroll 8
        for (int jl = 0; jl < 64; jl++) {
            float4 w  = *(const float4*)&ST[(kb*64 + jl) * 68 + i0];
            ulonglong2 vv = *(const ulonglong2*)&kvb[jl*68 + j0];
            u64 w0 = dup2(w.x), w1 = dup2(w.y), w2 = dup2(w.z), w3 = dup2(w.w);
            fma2(acc2[0][0],w0,vv.x); fma2(acc2[0][1],w0,vv.y);
            fma2(acc2[1][0],w1,vv.x); fma2(acc2[1][1],w1,vv.y);
            fma2(acc2[2][0],w2,vv.x); fma2(acc2[2][1],w2,vv.y);
            fma2(acc2[3][0],w3,vv.x); fma2(acc2[3][1],w3,vv.y);
        }
        __syncthreads();
    }
    float* dst = g_sparse + ((size_t)bh * LL + qb * BSS) * DHH;
#pragma unroll
    for (int ii = 0; ii < 4; ii++) {
        ulonglong2 st;
        st.x = acc2[ii][0]; st.y = acc2[ii][1];
        *(ulonglong2*)&dst[(i0 + ii) * DHH + j0] = st;
    }
}

__global__ void linear_kv_kernel() {
    int bh = blockIdx.y;
    __shared__ float pk[64][68];
    __shared__ float vvs[64][68];
    __shared__ float ksred[64];
    int t = threadIdx.x;
    int tx = t & 15, ty = t >> 4;
    int lrow = t >> 2, lg = t & 3;
    u64 acc[4][2];
#pragma unroll
    for (int i = 0; i < 4; i++) { acc[i][0] = 0ull; acc[i][1] = 0ull; }
    float ksp[16];
#pragma unroll
    for (int c = 0; c < 16; c++) ksp[c] = 0.f;
    if (t < 64) ksred[t] = 0.f;

    for (int sub = 0; sub < 4; sub++) {
        size_t l0 = (size_t)blockIdx.x * 256 + sub * 64;
        const float* ks = g_k + ((size_t)bh * LL + l0 + lrow) * DHH + lg * 16;
        const float* vs = g_v + ((size_t)bh * LL + l0 + lrow) * DHH + lg * 16;
        __syncthreads();
#pragma unroll
        for (int c = 0; c < 16; c += 4) {
            float4 kx = *(const float4*)(ks + c);
            float4 vx = *(const float4*)(vs + c);
            float p0 = kx.x > 0.f ? kx.x + 1.f : expm1f(kx.x) + 1.f;
            float p1 = kx.y > 0.f ? kx.y + 1.f : expm1f(kx.y) + 1.f;
            float p2 = kx.z > 0.f ? kx.z + 1.f : expm1f(kx.z) + 1.f;
            float p3 = kx.w > 0.f ? kx.w + 1.f : expm1f(kx.w) + 1.f;
            pk[lrow][lg*16 + c    ] = p0;
            pk[lrow][lg*16 + c + 1] = p1;
            pk[lrow][lg*16 + c + 2] = p2;
            pk[lrow][lg*16 + c + 3] = p3;
            ksp[c] += p0; ksp[c+1] += p1; ksp[c+2] += p2; ksp[c+3] += p3;
            *(float4*)&vvs[lrow][lg*16 + c] = vx;
        }
        __syncthreads();
#pragma unroll 8
        for (int l = 0; l < 64; l++) {
            float4 a = *(const float4*)&pk[l][ty << 2];
            ulonglong2 b = *(const ulonglong2*)&vvs[l][tx << 2];
            u64 a0 = dup2(a.x), a1 = dup2(a.y), a2 = dup2(a.z), a3 = dup2(a.w);
            fma2(acc[0][0],a0,b.x); fma2(acc[0][1],a0,b.y);
            fma2(acc[1][0],a1,b.x); fma2(acc[1][1],a1,b.y);
            fma2(acc[2][0],a2,b.x); fma2(acc[2][1],a2,b.y);
            fma2(acc[3][0],a3,b.x); fma2(acc[3][1],a3,b.y);
        }
    }
    __syncthreads();
#pragma unroll
    for (int c = 0; c < 16; c++) atomicAdd(&ksred[lg*16 + c], ksp[c]);
    __syncthreads();
    float* kvo = g_kv + (size_t)bh * DHH * DHH;
#pragma unroll
    for (int di = 0; di < 4; di++) {
        float2 v0 = unp2(acc[di][0]), v1 = unp2(acc[di][1]);
        atomicAdd(&kvo[((ty<<2) + di) * DHH + (tx<<2) + 0], v0.x);
        atomicAdd(&kvo[((ty<<2) + di) * DHH + (tx<<2) + 1], v0.y);
        atomicAdd(&kvo[((ty<<2) + di) * DHH + (tx<<2) + 2], v1.x);
        atomicAdd(&kvo[((ty<<2) + di) * DHH + (tx<<2) + 3], v1.y);
    }
    if (t < 64) atomicAdd(&g_ksum[(size_t)bh * DHH + t], ksred[t]);
}

__global__ void linear_out_blend_kernel(const float* __restrict__ alog) {
    int bh = blockIdx.y;
    int b = bh >> 3, h = bh & 7;
    __shared__ float kvs[64][64];
    __shared__ float kss[64];
    int t = threadIdx.x;
    for (int e = t; e < 4096; e += 256) kvs[e >> 6][e & 63] = g_kv[(size_t)bh * 4096 + e];
    if (t < 64) kss[t] = g_ksum[(size_t)bh * DHH + t];
    __syncthreads();
    float alpha = 1.f / (1.f + expf(-alog[h]));
    int warp = t >> 5, lane = t & 31;
    int l = blockIdx.x * 8 + warp;
    const float* qrow = g_q + ((size_t)bh * LL + l) * DHH;
    float x0 = qrow[lane], x1 = qrow[lane + 32];
    float p0 = x0 > 0.f ? x0 + 1.f : expm1f(x0) + 1.f;
    float p1 = x1 > 0.f ? x1 + 1.f : expm1f(x1) + 1.f;
    float den = p0 * kss[lane] + p1 * kss[lane + 32];
    for (int o = 16; o; o >>= 1) den += __shfl_xor_sync(0xffffffffu, den, o);
    float a0 = 0.f, a1 = 0.f;
#pragma unroll
    for (int d = 0; d < 64; d++) {
        float pv = (d < 32) ? __shfl_sync(0xffffffffu, p0, d)
                            : __shfl_sync(0xffffffffu, p1, d - 32);
        a0 += pv * kvs[d][lane];
        a1 += pv * kvs[d][lane + 32];
    }
    float dd = den + 1e-6f;
    const float* sp = g_sparse + ((size_t)bh * LL + l) * DHH;
    float* dst = g_blend + ((size_t)b * LL + l) * DMM + h * DHH;
    dst[lane]      = alpha * sp[lane]      + (1.f - alpha) * (a0 / dd);
    dst[lane + 32] = alpha * sp[lane + 32] + (1.f - alpha) * (a1 / dd);
}

extern "C" void kernel_launch(void* const* d_in, const int* in_sizes, int n_in,
                              void* d_out, int out_size) {
    const float* hs  = (const float*)d_in[0];
    const float* pb  = (const float*)d_in[1];
    const float* Wq  = (const float*)d_in[2];
    const float* Wk  = (const float*)d_in[3];
    const float* Wv  = (const float*)d_in[4];
    const float* Wo  = (const float*)d_in[5];
    const float* Wrq = (const float*)d_in[6];
    const float* Wrk = (const float*)d_in[7];
    const float* bsc = (const float*)d_in[8];
    const float* alo = (const float*)d_in[9];
    float* out = (float*)d_out;

    static int init_done = 0;
    if (!init_done) {
        cudaFuncSetAttribute(sparse_attn_kernel,
                             cudaFuncAttributeMaxDynamicSharedMemorySize, SMEM_K5);
        init_done = 1;
    }

    void *gq, *gk, *gv, *gbl, *gkv, *gks;
    cudaGetSymbolAddress(&gq,  g_q);
    cudaGetSymbolAddress(&gk,  g_k);
    cudaGetSymbolAddress(&gv,  g_v);
    cudaGetSymbolAddress(&gbl, g_blend);
    cudaGetSymbolAddress(&gkv, g_kv);
    cudaGetSymbolAddress(&gks, g_ksum);

    cudaMemsetAsync(gkv, 0, sizeof(float) * BB*HH*DHH*DHH);
    cudaMemsetAsync(gks, 0, sizeof(float) * BB*HH*DHH);

    dim3 gg(4, 128);
    gemm_xwt_kernel<<<gg, 256>>>(hs, Wq, (float*)gq, DMM, 1);
    gemm_xwt_kernel<<<gg, 256>>>(hs, Wk, (float*)gk, DMM, 1);
    gemm_xwt_kernel<<<gg, 256>>>(hs, Wv, (float*)gv, DMM, 1);

    pool_proj_kernel<<<dim3(NBB, BB*HH), 256>>>(Wrq, Wrk);
    pool_bias_kernel<<<dim3(NBB*NBB, HH), 128>>>(pb);
    router_topk_kernel<<<BB*HH, 256>>>(bsc);

    sparse_attn_kernel<<<dim3(NBB, BB*HH), 256, SMEM_K5>>>(pb);

    linear_kv_kernel<<<dim3(LL/256, BB*HH), 256>>>();
    linear_out_blend_kernel<<<dim3(LL/8, BB*HH), 256>>>(alo);

    gemm_xwt_kernel<<<gg, 256>>>((const float*)gbl, Wo, out, DMM, 0);
}

// round 6
// speedup vs baseline: 1.1931x; 1.1931x over previous
#include <cuda_runtime.h>
#include <cuda_bf16.h>
#include <math.h>
#include <stdint.h>

#define BB   2
#define HH   8
#define LL   4096
#define DMM  512
#define DHH  64
#define NBB  64
#define BSS  64
#define KPQ  9
#define GK   512

__device__ float g_q[BB*HH*LL*DHH];
__device__ float g_k[BB*HH*LL*DHH];
__device__ float g_v[BB*HH*LL*DHH];
__device__ float g_qproj[BB*HH*NBB*DHH];
__device__ float g_kproj[BB*HH*NBB*DHH];
__device__ float g_pbias[HH*NBB*NBB];
__device__ int   g_sel[BB*HH*NBB*KPQ];
__device__ float g_sparse[BB*HH*LL*DHH];
__device__ float g_kv[BB*HH*DHH*DHH];
__device__ float g_ksum[BB*HH*DHH];
__device__ float g_blend[BB*LL*DMM];
__device__ __nv_bfloat16 g_xhi[BB*LL*DMM];
__device__ __nv_bfloat16 g_xmi[BB*LL*DMM];
__device__ __nv_bfloat16 g_xlo[BB*LL*DMM];
__device__ __nv_bfloat16 g_whi[4*DMM*DMM];
__device__ __nv_bfloat16 g_wmi[4*DMM*DMM];
__device__ __nv_bfloat16 g_wlo[4*DMM*DMM];

__device__ __forceinline__ uint32_t smem_u32(const void* p) {
    uint32_t a;
    asm("{ .reg .u64 t; cvta.to.shared.u64 t, %1; cvt.u32.u64 %0, t; }" : "=r"(a) : "l"(p));
    return a;
}
#define LDMX4(r0,r1,r2,r3,addr) \
    asm volatile("ldmatrix.sync.aligned.m8n8.x4.shared.b16 {%0,%1,%2,%3}, [%4];" \
        : "=r"(r0), "=r"(r1), "=r"(r2), "=r"(r3) : "r"(addr))
#define MMA16816(c, a, b0, b1) \
    asm volatile("mma.sync.aligned.m16n8k16.row.col.f32.bf16.bf16.f32 " \
        "{%0,%1,%2,%3}, {%4,%5,%6,%7}, {%8,%9}, {%0,%1,%2,%3};" \
        : "+f"((c)[0]), "+f"((c)[1]), "+f"((c)[2]), "+f"((c)[3]) \
        : "r"((a)[0]), "r"((a)[1]), "r"((a)[2]), "r"((a)[3]), "r"(b0), "r"(b1))

// ---------------- fp32 -> (bf16 hi, mid, lo) — each split exact in fp32 ----------------
__global__ void cvt3_kernel(const float* __restrict__ src,
                            __nv_bfloat16* __restrict__ hi,
                            __nv_bfloat16* __restrict__ mi,
                            __nv_bfloat16* __restrict__ lo, int n4) {
    int i = blockIdx.x * blockDim.x + threadIdx.x;
    if (i >= n4) return;
    float4 v = ((const float4*)src)[i];
    __nv_bfloat16 h[4], m[4], l[4];
    float xs[4] = {v.x, v.y, v.z, v.w};
#pragma unroll
    for (int c = 0; c < 4; c++) {
        h[c] = __float2bfloat16_rn(xs[c]);
        float r1 = xs[c] - __bfloat162float(h[c]);
        m[c] = __float2bfloat16_rn(r1);
        float r2 = r1 - __bfloat162float(m[c]);
        l[c] = __float2bfloat16_rn(r2);
    }
    ((uint2*)hi)[i] = *(uint2*)h;
    ((uint2*)mi)[i] = *(uint2*)m;
    ((uint2*)lo)[i] = *(uint2*)l;
}

// ---------------- 3-way split-bf16 MMA GEMM: C = X @ W^T ----------------
// CTA 128m x 128n, 8 warps (4m x 2n), warp tile 32m x 64n, K-chunk 32.
// mode 0: row-major out [M, 512] (out0). mode 1: BHLD scatter (fused QKV, N=1536).
#define TSTRIDE 40
#define TOFF(i) ((i) * 128 * TSTRIDE)
#define MMA_SMEM (6 * 128 * TSTRIDE * 2)

__global__ void __launch_bounds__(256) mma_gemm_kernel(
        const __nv_bfloat16* __restrict__ ahi, const __nv_bfloat16* __restrict__ ami,
        const __nv_bfloat16* __restrict__ alo,
        const __nv_bfloat16* __restrict__ bhi, const __nv_bfloat16* __restrict__ bmi,
        const __nv_bfloat16* __restrict__ blo,
        float* __restrict__ out0, float* __restrict__ out1, float* __restrict__ out2,
        int mode) {
    extern __shared__ __align__(16) __nv_bfloat16 smb[];
    __nv_bfloat16* sAh = smb + TOFF(0);
    __nv_bfloat16* sAm = smb + TOFF(1);
    __nv_bfloat16* sAl = smb + TOFF(2);
    __nv_bfloat16* sBh = smb + TOFF(3);
    __nv_bfloat16* sBm = smb + TOFF(4);
    __nv_bfloat16* sBl = smb + TOFF(5);

    int t = threadIdx.x;
    int wid = t >> 5, lane = t & 31;
    int wm = wid & 3, wn = wid >> 2;
    int m0 = blockIdx.y << 7, n0 = blockIdx.x << 7;

    float acc[2][8][4];
#pragma unroll
    for (int i = 0; i < 2; i++)
#pragma unroll
        for (int j = 0; j < 8; j++)
#pragma unroll
            for (int c = 0; c < 4; c++) acc[i][j][c] = 0.f;

    int lr = t >> 1;
    int lh = (t & 1) << 4;

    uint32_t aRow = lane & 15;
    uint32_t aCol = ((lane >> 4) & 1) << 3;
    uint32_t bRow = (((lane >> 4) & 1) << 3) + (lane & 7);
    uint32_t bCol = ((lane >> 3) & 1) << 3;

    for (int kc = 0; kc < 16; kc++) {
        int kg = kc << 5;
        size_t aoff = (size_t)(m0 + lr) * GK + kg + lh;
        size_t boff = (size_t)(n0 + lr) * GK + kg + lh;
        __syncthreads();
#pragma unroll
        for (int half = 0; half < 2; half++) {
            int o = half * 8;
            *(uint4*)&sAh[lr*TSTRIDE + lh + o] = *(const uint4*)(ahi + aoff + o);
            *(uint4*)&sAm[lr*TSTRIDE + lh + o] = *(const uint4*)(ami + aoff + o);
            *(uint4*)&sAl[lr*TSTRIDE + lh + o] = *(const uint4*)(alo + aoff + o);
            *(uint4*)&sBh[lr*TSTRIDE + lh + o] = *(const uint4*)(bhi + boff + o);
            *(uint4*)&sBm[lr*TSTRIDE + lh + o] = *(const uint4*)(bmi + boff + o);
            *(uint4*)&sBl[lr*TSTRIDE + lh + o] = *(const uint4*)(blo + boff + o);
        }
        __syncthreads();

#pragma unroll
        for (int ks = 0; ks < 2; ks++) {
            int kk = ks << 4;
            uint32_t ah[2][4], am[2][4], al[2][4];
#pragma unroll
            for (int mt = 0; mt < 2; mt++) {
                int ar = (wm*32 + mt*16 + aRow) * TSTRIDE + kk + aCol;
                uint32_t adh = smem_u32(&sAh[ar]);
                uint32_t adm = smem_u32(&sAm[ar]);
                uint32_t adl = smem_u32(&sAl[ar]);
                LDMX4(ah[mt][0], ah[mt][1], ah[mt][2], ah[mt][3], adh);
                LDMX4(am[mt][0], am[mt][1], am[mt][2], am[mt][3], adm);
                LDMX4(al[mt][0], al[mt][1], al[mt][2], al[mt][3], adl);
            }
#pragma unroll
            for (int np = 0; np < 4; np++) {
                uint32_t bh4[4], bm4[4], bl4[4];
                int br = (wn*64 + np*16 + bRow) * TSTRIDE + kk + bCol;
                uint32_t bdh = smem_u32(&sBh[br]);
                uint32_t bdm = smem_u32(&sBm[br]);
                uint32_t bdl = smem_u32(&sBl[br]);
                LDMX4(bh4[0], bh4[1], bh4[2], bh4[3], bdh);
                LDMX4(bm4[0], bm4[1], bm4[2], bm4[3], bdm);
                LDMX4(bl4[0], bl4[1], bl4[2], bl4[3], bdl);
#pragma unroll
                for (int mt = 0; mt < 2; mt++) {
                    float* c0 = acc[mt][np*2];
                    float* c1 = acc[mt][np*2+1];
                    MMA16816(c0, ah[mt], bh4[0], bh4[1]);
                    MMA16816(c1, ah[mt], bh4[2], bh4[3]);
                    MMA16816(c0, ah[mt], bm4[0], bm4[1]);
                    MMA16816(c1, ah[mt], bm4[2], bm4[3]);
                    MMA16816(c0, am[mt], bh4[0], bh4[1]);
                    MMA16816(c1, am[mt], bh4[2], bh4[3]);
                    MMA16816(c0, am[mt], bm4[0], bm4[1]);
                    MMA16816(c1, am[mt], bm4[2], bm4[3]);
                    MMA16816(c0, ah[mt], bl4[0], bl4[1]);
                    MMA16816(c1, ah[mt], bl4[2], bl4[3]);
                    MMA16816(c0, al[mt], bh4[0], bh4[1]);
                    MMA16816(c1, al[mt], bh4[2], bh4[3]);
                }
            }
        }
    }

#pragma unroll
    for (int mt = 0; mt < 2; mt++)
#pragma unroll
        for (int nt = 0; nt < 8; nt++) {
            int mg = m0 + wm*32 + mt*16 + (lane >> 2);
            int ng = n0 + wn*64 + nt*8 + ((lane & 3) << 1);
            float* c = acc[mt][nt];
            if (mode == 0) {
                *(float2*)(out0 + (size_t)mg * DMM + ng) = make_float2(c[0], c[1]);
                *(float2*)(out0 + (size_t)(mg + 8) * DMM + ng) = make_float2(c[2], c[3]);
            } else {
                int hh = ng >> 6;
                float* buf = (hh < 8) ? out0 : (hh < 16) ? out1 : out2;
                int h = hh & 7, col = ng & 63;
                int b = mg >> 12, l = mg & 4095;
                float* dp = buf + (((size_t)(b*HH + h) * LL + l) << 6) + col;
                *(float2*)dp = make_float2(c[0], c[1]);
                *(float2*)(dp + (8 << 6)) = make_float2(c[2], c[3]);
            }
        }
}

// ================= R2 kernels (known good) =================
#define FMA16(acc,a,b) { \
  acc[0][0]+=a.x*b.x; acc[0][1]+=a.x*b.y; acc[0][2]+=a.x*b.z; acc[0][3]+=a.x*b.w; \
  acc[1][0]+=a.y*b.x; acc[1][1]+=a.y*b.y; acc[1][2]+=a.y*b.z; acc[1][3]+=a.y*b.w; \
  acc[2][0]+=a.z*b.x; acc[2][1]+=a.z*b.y; acc[2][2]+=a.z*b.z; acc[2][3]+=a.z*b.w; \
  acc[3][0]+=a.w*b.x; acc[3][1]+=a.w*b.y; acc[3][2]+=a.w*b.z; acc[3][3]+=a.w*b.w; }

__global__ void pool_proj_kernel(const float* __restrict__ Wrq, const float* __restrict__ Wrk) {
    int qb = blockIdx.x, bh = blockIdx.y;
    int t = threadIdx.x;
    int d = t & 63, g = t >> 6;
    __shared__ float sq[4][64], sk[4][64];
    __shared__ float qp[64], kp[64];
    const float* qb_ = g_q + ((size_t)bh * LL + qb * BSS + g * 16) * DHH;
    const float* kb_ = g_k + ((size_t)bh * LL + qb * BSS + g * 16) * DHH;
    float aq = 0.f, ak = 0.f;
#pragma unroll 4
    for (int i = 0; i < 16; i++) { aq += qb_[i*DHH + d]; ak += kb_[i*DHH + d]; }
    sq[g][d] = aq; sk[g][d] = ak;
    __syncthreads();
    if (t < 64) {
        qp[d] = (sq[0][d]+sq[1][d]+sq[2][d]+sq[3][d]) * (1.f / BSS);
        kp[d] = (sk[0][d]+sk[1][d]+sk[2][d]+sk[3][d]) * (1.f / BSS);
    }
    __syncthreads();
    float pq = 0.f, pk2 = 0.f;
#pragma unroll 4
    for (int e = g*16; e < g*16 + 16; e++) {
        pq  += qp[e] * Wrq[d*DHH + e];
        pk2 += kp[e] * Wrk[d*DHH + e];
    }
    sq[g][d] = pq; sk[g][d] = pk2;
    __syncthreads();
    if (t < 64) {
        g_qproj[((size_t)bh * NBB + qb) * DHH + d] = sq[0][d]+sq[1][d]+sq[2][d]+sq[3][d];
        g_kproj[((size_t)bh * NBB + qb) * DHH + d] = sk[0][d]+sk[1][d]+sk[2][d]+sk[3][d];
    }
}

__global__ void pool_bias_kernel(const float* __restrict__ pb) {
    int h = blockIdx.y;
    int qb = blockIdx.x >> 6, kb = blockIdx.x & 63;
    const float* base = pb + ((size_t)h * LL + qb * BSS) * LL + kb * BSS;
    int t = threadIdx.x;
    int j = t & 63, i0 = t >> 6;
    float s = 0.f;
    for (int i = i0; i < BSS; i += 2) s += base[(size_t)i * LL + j];
    __shared__ float red[128];
    red[t] = s;
    __syncthreads();
    if (t < 64) red[t] += red[t + 64];
    __syncthreads();
    if (t < 32) {
        float v = red[t] + red[t + 32];
        for (int o = 16; o; o >>= 1) v += __shfl_xor_sync(0xffffffffu, v, o);
        if (t == 0) g_pbias[((size_t)h * NBB + qb) * NBB + kb] = v * (1.f / (BSS * BSS));
    }
}

__global__ void router_topk_kernel(const float* __restrict__ bscale_p) {
    __shared__ float sc[NBB][NBB];
    int bh = blockIdx.x;
    int h = bh & 7;
    float bsc = *bscale_p;
    const float* qp = g_qproj + (size_t)bh * NBB * DHH;
    const float* kp = g_kproj + (size_t)bh * NBB * DHH;
    for (int e = threadIdx.x; e < NBB * NBB; e += 256) {
        int qb = e >> 6, kb = e & 63;
        float s = 0.f;
        for (int d = 0; d < DHH; d++) s += qp[qb*DHH + d] * kp[kb*DHH + d];
        sc[qb][kb] = s * 0.125f + bsc * g_pbias[((size_t)h * NBB + qb) * NBB + kb];
    }
    __syncthreads();
    int warp = threadIdx.x >> 5, lane = threadIdx.x & 31;
    for (int r = warp; r < NBB; r += 8) {
        float v0 = sc[r][lane], v1 = sc[r][lane + 32];
        int i0 = lane, i1 = lane + 32;
        for (int tk = 0; tk < KPQ; tk++) {
            float bv; int bi;
            if (v0 > v1 || (v0 == v1 && i0 < i1)) { bv = v0; bi = i0; }
            else { bv = v1; bi = i1; }
            for (int off = 16; off; off >>= 1) {
                float ov = __shfl_xor_sync(0xffffffffu, bv, off);
                int   oi = __shfl_xor_sync(0xffffffffu, bi, off);
                if (ov > bv || (ov == bv && oi < bi)) { bv = ov; bi = oi; }
            }
            if (lane == 0) g_sel[((size_t)bh * NBB + r) * KPQ + tk] = bi;
            if (i0 == bi) v0 = -INFINITY;
            if (i1 == bi) v1 = -INFINITY;
        }
    }
}

__device__ __forceinline__ float fq_clip(float r) {
    return fminf(fmaxf(r, -128.f), 127.f);
}

__device__ __forceinline__ void load_fq_block(const float* __restrict__ src_base,
                                              float* __restrict__ dst,
                                              int lrow, int lg, int transpose) {
    const float* src = src_base + (size_t)lrow * DHH + lg * 16;
    float x[16];
    float mx = 0.f;
#pragma unroll
    for (int c = 0; c < 16; c += 4) {
        float4 v = *(const float4*)(src + c);
        x[c] = v.x; x[c+1] = v.y; x[c+2] = v.z; x[c+3] = v.w;
    }
#pragma unroll
    for (int c = 0; c < 16; c++) mx = fmaxf(mx, fabsf(x[c]));
    mx = fmaxf(mx, __shfl_xor_sync(0xffffffffu, mx, 1));
    mx = fmaxf(mx, __shfl_xor_sync(0xffffffffu, mx, 2));
    float scale = fmaxf(mx, 1e-8f) / 127.0f;
    if (transpose) {
#pragma unroll
        for (int c = 0; c < 16; c++)
            dst[(lg*16 + c) * 68 + lrow] = fq_clip(rintf(x[c] / scale)) * scale;
    } else {
#pragma unroll
        for (int c = 0; c < 16; c += 4) {
            float4 o;
            o.x = fq_clip(rintf(x[c  ] / scale)) * scale;
            o.y = fq_clip(rintf(x[c+1] / scale)) * scale;
            o.z = fq_clip(rintf(x[c+2] / scale)) * scale;
            o.w = fq_clip(rintf(x[c+3] / scale)) * scale;
            *(float4*)&dst[lrow * 68 + lg*16 + c] = o;
        }
    }
}

#define SMEM_K5 ((576*68 + 64*68 + 64*68 + 192) * 4)

__global__ void sparse_attn_kernel(const float* __restrict__ pb) {
    extern __shared__ float sm[];
    float* ST   = sm;
    float* qsT  = ST  + 576 * 68;
    float* kvb  = qsT + 64 * 68;
    float* rowm = kvb + 64 * 68;
    float* rowz = rowm + 64;
    float* rowsc= rowz + 64;

    int qb = blockIdx.x, bh = blockIdx.y;
    int h = bh & 7;
    int t = threadIdx.x;
    int tx = t & 15, ty = t >> 4;
    int lrow = t >> 2, lg = t & 3;

    load_fq_block(g_q + ((size_t)bh * LL + qb * BSS) * DHH, qsT, lrow, lg, 1);
    __syncthreads();

    const int selbase = (bh * NBB + qb) * KPQ;
    int i0 = ty << 2, j0 = tx << 2;

    for (int kb = 0; kb < KPQ; kb++) {
        int kidx = g_sel[selbase + kb];
        load_fq_block(g_k + ((size_t)bh * LL + kidx * BSS) * DHH, kvb, lrow, lg, 1);
        __syncthreads();
        float acc[4][4];
#pragma unroll
        for (int i = 0; i < 4; i++)
#pragma unroll
            for (int j = 0; j < 4; j++) acc[i][j] = 0.f;
#pragma unroll 8
        for (int d = 0; d < 64; d++) {
            float4 a = *(const float4*)&qsT[d*68 + i0];
            float4 b = *(const float4*)&kvb[d*68 + j0];
            FMA16(acc, a, b);
        }
        const float* brow = pb + ((size_t)h * LL + qb * BSS + i0) * LL + (size_t)kidx * BSS + j0;
#pragma unroll
        for (int ii = 0; ii < 4; ii++) {
            float4 pv = *(const float4*)(brow + (size_t)ii * LL);
            acc[ii][0] += pv.x; acc[ii][1] += pv.y; acc[ii][2] += pv.z; acc[ii][3] += pv.w;
        }
#pragma unroll
        for (int jj = 0; jj < 4; jj++)
            *(float4*)&ST[(kb*64 + j0 + jj) * 68 + i0] =
                make_float4(acc[0][jj], acc[1][jj], acc[2][jj], acc[3][jj]);
        __syncthreads();
    }

    {
        float m = -INFINITY;
        for (int j = lg; j < 576; j += 4) m = fmaxf(m, ST[j*68 + lrow]);
        m = fmaxf(m, __shfl_xor_sync(0xffffffffu, m, 1));
        m = fmaxf(m, __shfl_xor_sync(0xffffffffu, m, 2));
        float z = 0.f;
        for (int j = lg; j < 576; j += 4) z += expf(ST[j*68 + lrow] - m);
        z += __shfl_xor_sync(0xffffffffu, z, 1);
        z += __shfl_xor_sync(0xffffffffu, z, 2);
        if (lg == 0) {
            rowm[lrow] = m; rowz[lrow] = z;
            rowsc[lrow] = fmaxf(1.0f / z, 1e-8f) / 127.0f;
        }
    }
    __syncthreads();

    for (int e = t; e < 576 * 64; e += 256) {
        int i = e & 63, j = e >> 6;
        float w = expf(ST[j*68 + i] - rowm[i]) / rowz[i];
        float sc = rowsc[i];
        ST[j*68 + i] = fq_clip(rintf(w / sc)) * sc;
    }
    __syncthreads();

    float acc2[4][4];
#pragma unroll
    for (int i = 0; i < 4; i++)
#pragma unroll
        for (int j = 0; j < 4; j++) acc2[i][j] = 0.f;
    for (int kb = 0; kb < KPQ; kb++) {
        int kidx = g_sel[selbase + kb];
        load_fq_block(g_v + ((size_t)bh * LL + kidx * BSS) * DHH, kvb, lrow, lg, 0);
        __syncthreads();
#pragma unroll 8
        for (int jl = 0; jl < 64; jl++) {
            float4 w  = *(const float4*)&ST[(kb*64 + jl) * 68 + i0];
            float4 vv = *(const float4*)&kvb[jl*68 + j0];
            FMA16(acc2, w, vv);
        }
        __syncthreads();
    }
    float* dst = g_sparse + ((size_t)bh * LL + qb * BSS) * DHH;
#pragma unroll
    for (int ii = 0; ii < 4; ii++)
        *(float4*)&dst[(i0 + ii) * DHH + j0] =
            make_float4(acc2[ii][0], acc2[ii][1], acc2[ii][2], acc2[ii][3]);
}

__global__ void linear_kv_kernel() {
    int bh = blockIdx.y;
    __shared__ float pk[64][68];
    __shared__ float vvs[64][68];
    __shared__ float ksred[64];
    int t = threadIdx.x;
    int tx = t & 15, ty = t >> 4;
    int lrow = t >> 2, lg = t & 3;
    float acc[4][4];
#pragma unroll
    for (int i = 0; i < 4; i++)
#pragma unroll
        for (int j = 0; j < 4; j++) acc[i][j] = 0.f;
    float ksp[16];
#pragma unroll
    for (int c = 0; c < 16; c++) ksp[c] = 0.f;
    if (t < 64) ksred[t] = 0.f;

    for (int sub = 0; sub < 4; sub++) {
        size_t l0 = (size_t)blockIdx.x * 256 + sub * 64;
        const float* ks = g_k + ((size_t)bh * LL + l0 + lrow) * DHH + lg * 16;
        const float* vs = g_v + ((size_t)bh * LL + l0 + lrow) * DHH + lg * 16;
        __syncthreads();
#pragma unroll
        for (int c = 0; c < 16; c += 4) {
            float4 kx = *(const float4*)(ks + c);
            float4 vx = *(const float4*)(vs + c);
            float p0 = kx.x > 0.f ? kx.x + 1.f : expm1f(kx.x) + 1.f;
            float p1 = kx.y > 0.f ? kx.y + 1.f : expm1f(kx.y) + 1.f;
            float p2 = kx.z > 0.f ? kx.z + 1.f : expm1f(kx.z) + 1.f;
            float p3 = kx.w > 0.f ? kx.w + 1.f : expm1f(kx.w) + 1.f;
            pk[lrow][lg*16 + c    ] = p0;
            pk[lrow][lg*16 + c + 1] = p1;
            pk[lrow][lg*16 + c + 2] = p2;
            pk[lrow][lg*16 + c + 3] = p3;
            ksp[c] += p0; ksp[c+1] += p1; ksp[c+2] += p2; ksp[c+3] += p3;
            *(float4*)&vvs[lrow][lg*16 + c] = vx;
        }
        __syncthreads();
#pragma unroll 8
        for (int l = 0; l < 64; l++) {
            float4 a = *(const float4*)&pk[l][ty << 2];
            float4 b = *(const float4*)&vvs[l][tx << 2];
            FMA16(acc, a, b);
        }
    }
    __syncthreads();
#pragma unroll
    for (int c = 0; c < 16; c++) atomicAdd(&ksred[lg*16 + c], ksp[c]);
    __syncthreads();
    float* kvo = g_kv + (size_t)bh * DHH * DHH;
#pragma unroll
    for (int di = 0; di < 4; di++)
#pragma unroll
        for (int mi = 0; mi < 4; mi++)
            atomicAdd(&kvo[((ty<<2) + di) * DHH + (tx<<2) + mi], acc[di][mi]);
    if (t < 64) atomicAdd(&g_ksum[(size_t)bh * DHH + t], ksred[t]);
}

__global__ void linear_out_blend_kernel(const float* __restrict__ alog) {
    int bh = blockIdx.y;
    int b = bh >> 3, h = bh & 7;
    __shared__ float kvs[64][64];
    __shared__ float kss[64];
    int t = threadIdx.x;
    for (int e = t; e < 4096; e += 256) kvs[e >> 6][e & 63] = g_kv[(size_t)bh * 4096 + e];
    if (t < 64) kss[t] = g_ksum[(size_t)bh * DHH + t];
    __syncthreads();
    float alpha = 1.f / (1.f + expf(-alog[h]));
    int warp = t >> 5, lane = t & 31;
    int l = blockIdx.x * 8 + warp;
    const float* qrow = g_q + ((size_t)bh * LL + l) * DHH;
    float x0 = qrow[lane], x1 = qrow[lane + 32];
    float p0 = x0 > 0.f ? x0 + 1.f : expm1f(x0) + 1.f;
    float p1 = x1 > 0.f ? x1 + 1.f : expm1f(x1) + 1.f;
    float den = p0 * kss[lane] + p1 * kss[lane + 32];
    for (int o = 16; o; o >>= 1) den += __shfl_xor_sync(0xffffffffu, den, o);
    float a0 = 0.f, a1 = 0.f;
#pragma unroll
    for (int d = 0; d < 64; d++) {
        float pv = (d < 32) ? __shfl_sync(0xffffffffu, p0, d)
                            : __shfl_sync(0xffffffffu, p1, d - 32);
        a0 += pv * kvs[d][lane];
        a1 += pv * kvs[d][lane + 32];
    }
    float dd = den + 1e-6f;
    const float* sp = g_sparse + ((size_t)bh * LL + l) * DHH;
    float* dst = g_blend + ((size_t)b * LL + l) * DMM + h * DHH;
    dst[lane]      = alpha * sp[lane]      + (1.f - alpha) * (a0 / dd);
    dst[lane + 32] = alpha * sp[lane + 32] + (1.f - alpha) * (a1 / dd);
}

extern "C" void kernel_launch(void* const* d_in, const int* in_sizes, int n_in,
                              void* d_out, int out_size) {
    const float* hs  = (const float*)d_in[0];
    const float* pb  = (const float*)d_in[1];
    const float* Wq  = (const float*)d_in[2];
    const float* Wk  = (const float*)d_in[3];
    const float* Wv  = (const float*)d_in[4];
    const float* Wo  = (const float*)d_in[5];
    const float* Wrq = (const float*)d_in[6];
    const float* Wrk = (const float*)d_in[7];
    const float* bsc = (const float*)d_in[8];
    const float* alo = (const float*)d_in[9];
    float* out = (float*)d_out;

    cudaFuncSetAttribute(sparse_attn_kernel,
                         cudaFuncAttributeMaxDynamicSharedMemorySize, SMEM_K5);
    cudaFuncSetAttribute(mma_gemm_kernel,
                         cudaFuncAttributeMaxDynamicSharedMemorySize, MMA_SMEM);

    void *gq, *gk, *gv, *gbl, *gkv, *gks, *gxh, *gxm, *gxl, *gwh, *gwm, *gwl;
    cudaGetSymbolAddress(&gq,  g_q);
    cudaGetSymbolAddress(&gk,  g_k);
    cudaGetSymbolAddress(&gv,  g_v);
    cudaGetSymbolAddress(&gbl, g_blend);
    cudaGetSymbolAddress(&gkv, g_kv);
    cudaGetSymbolAddress(&gks, g_ksum);
    cudaGetSymbolAddress(&gxh, g_xhi);
    cudaGetSymbolAddress(&gxm, g_xmi);
    cudaGetSymbolAddress(&gxl, g_xlo);
    cudaGetSymbolAddress(&gwh, g_whi);
    cudaGetSymbolAddress(&gwm, g_wmi);
    cudaGetSymbolAddress(&gwl, g_wlo);
    __nv_bfloat16* xhi = (__nv_bfloat16*)gxh;
    __nv_bfloat16* xmi = (__nv_bfloat16*)gxm;
    __nv_bfloat16* xlo = (__nv_bfloat16*)gxl;
    __nv_bfloat16* whi = (__nv_bfloat16*)gwh;
    __nv_bfloat16* wmi = (__nv_bfloat16*)gwm;
    __nv_bfloat16* wlo = (__nv_bfloat16*)gwl;

    cudaMemsetAsync(gkv, 0, sizeof(float) * BB*HH*DHH*DHH);
    cudaMemsetAsync(gks, 0, sizeof(float) * BB*HH*DHH);

    const int NX4 = BB*LL*DMM/4;
    const int NW4 = DMM*DMM/4;
    cvt3_kernel<<<(NX4+255)/256, 256>>>(hs, xhi, xmi, xlo, NX4);
    cvt3_kernel<<<(NW4+255)/256, 256>>>(Wq, whi,             wmi,             wlo,             NW4);
    cvt3_kernel<<<(NW4+255)/256, 256>>>(Wk, whi +   DMM*DMM, wmi +   DMM*DMM, wlo +   DMM*DMM, NW4);
    cvt3_kernel<<<(NW4+255)/256, 256>>>(Wv, whi + 2*DMM*DMM, wmi + 2*DMM*DMM, wlo + 2*DMM*DMM, NW4);
    cvt3_kernel<<<(NW4+255)/256, 256>>>(Wo, whi + 3*DMM*DMM, wmi + 3*DMM*DMM, wlo + 3*DMM*DMM, NW4);

    // fused QKV: N = 1536 (Wq|Wk|Wv stacked), scatter epilogue to g_q/g_k/g_v
    mma_gemm_kernel<<<dim3(12, 64), 256, MMA_SMEM>>>(
        xhi, xmi, xlo, whi, wmi, wlo, (float*)gq, (float*)gk, (float*)gv, 1);

    pool_proj_kernel<<<dim3(NBB, BB*HH), 256>>>(Wrq, Wrk);
    pool_bias_kernel<<<dim3(NBB*NBB, HH), 128>>>(pb);
    router_topk_kernel<<<BB*HH, 256>>>(bsc);

    sparse_attn_kernel<<<dim3(NBB, BB*HH), 256, SMEM_K5>>>(pb);

    linear_kv_kernel<<<dim3(LL/256, BB*HH), 256>>>();
    linear_out_blend_kernel<<<dim3(LL/8, BB*HH), 256>>>(alo);

    cvt3_kernel<<<(NX4+255)/256, 256>>>((const float*)gbl, xhi, xmi, xlo, NX4);
    mma_gemm_kernel<<<dim3(4, 64), 256, MMA_SMEM>>>(
        xhi, xmi, xlo, whi + 3*DMM*DMM, wmi + 3*DMM*DMM, wlo + 3*DMM*DMM, out, out, out, 0);
}